// round 13
// baseline (speedup 1.0000x reference)
#include <cuda_runtime.h>
#include <cuda_bf16.h>
#include <math_constants.h>

#define B 16
#define F 1024
#define H 16
#define D 64
#define L 8192
#define HD 1024            // H*D
#define NFC 32             // f-chunks for qkv split-K partials
#define NOC 64             // hd-chunks for out-proj partials
#define TBK 64             // K rows per block in fused K kernel
#define NCHK (L / TBK)     // 128 K-chunks per batch
#define TBV 128            // V rows per block in fused V kernel
#define NCV (L / TBV)      // 64 V-chunks per batch

// -------- device scratch (allocation-free: __device__ globals) --------
__device__ float g_qkv_part[3 * NFC * B * HD];      // 6 MB
__device__ float g_qkv[3 * B * HD];                 // q,k,v fp32 (+bias)
__device__ float g_logits[B * H * L];               // 8 MB fp32 logits
__device__ float g_cmax[B * H * NCHK];              // per-chunk max
__device__ float g_csum[B * H * NCHK];              // per-chunk sum(exp(l-m_c))
__device__ float g_m[B * H];
__device__ float g_s[B * H];
__device__ float g_accpart[B * H * NCV * D];        // 4 MB split AV partials
__device__ float g_o_part[NOC * B * F];             // 4 MB

__device__ __forceinline__ float bfr(float v) {
    // round-to-nearest-even through bf16, back to fp32 (matches astype(bf16))
    return __bfloat162float(__float2bfloat16(v));
}

// -------- QKV projection: split-K partial GEMV --------
__global__ __launch_bounds__(256) void qkv_partial_k(
        const float* __restrict__ x,
        const float* __restrict__ Wq, const float* __restrict__ Wk,
        const float* __restrict__ Wv) {
    const int fc = blockIdx.x, w = blockIdx.y;
    const float* Wt = (w == 0) ? Wq : ((w == 1) ? Wk : Wv);
    const int f0 = fc * (F / NFC);
    __shared__ float xs[F / NFC][B];
    const int tid = threadIdx.x;
    for (int i = tid; i < (F / NFC) * B; i += 256) {
        int f = i >> 4, b = i & 15;
        xs[f][b] = x[b * F + f0 + f];
    }
    __syncthreads();
    float4 acc[B];
#pragma unroll
    for (int b = 0; b < B; b++) acc[b] = make_float4(0.f, 0.f, 0.f, 0.f);
    const float4* wp = reinterpret_cast<const float4*>(Wt + (size_t)f0 * HD) + tid;
#pragma unroll 4
    for (int f = 0; f < F / NFC; f++) {
        float4 w4 = wp[(size_t)f * (HD / 4)];
#pragma unroll
        for (int b = 0; b < B; b++) {
            float xb = xs[f][b];
            acc[b].x = fmaf(xb, w4.x, acc[b].x);
            acc[b].y = fmaf(xb, w4.y, acc[b].y);
            acc[b].z = fmaf(xb, w4.z, acc[b].z);
            acc[b].w = fmaf(xb, w4.w, acc[b].w);
        }
    }
    float* dst = g_qkv_part + (size_t)(w * NFC + fc) * B * HD;
#pragma unroll
    for (int b = 0; b < B; b++)
        reinterpret_cast<float4*>(dst + b * HD)[tid] = acc[b];
}

// Reduce partials + bias into g_qkv; write new_idx (as float — output dtype).
__global__ __launch_bounds__(256) void qkv_reduce_k(
        const float* __restrict__ bq, const float* __restrict__ bk,
        const float* __restrict__ bv, const int* __restrict__ kvidx,
        float* __restrict__ oidx) {
    int g = blockIdx.x * 256 + threadIdx.x;      // < 3*B*HD = 49152
    int w = g >> 14;
    int r = g & 16383;
    int b = r >> 10;
    int col = r & 1023;
    float s = 0.f;
#pragma unroll 8
    for (int c = 0; c < NFC; c++)
        s += g_qkv_part[(size_t)(w * NFC + c) * B * HD + b * HD + col];
    const float* bias = (w == 0) ? bq : ((w == 1) ? bk : bv);
    g_qkv[(w * B + b) * HD + col] = s + bias[col];
    if (w == 0 && col == 0) oidx[b] = (float)(kvidx[b] + 1);
}

// -------- fused K: cache copy + slot scatter + logits + chunk softmax stats
// grid = B * NCHK blocks, 256 threads. Thread tid owns head h=tid/16,
// d-range (tid%16)*4..+3 of every 4KB row. Streaming hints (__ldcs/__stcs)
// on the 1 GB of once-only cache traffic; slot branch specialized out of
// the hot loop (slot falls in this chunk for only ~1/128 of blocks).
__global__ __launch_bounds__(256) void fused_k_kernel(
        const float* __restrict__ kk, const int* __restrict__ kvidx,
        float* __restrict__ okey) {
    const int blk = blockIdx.x;
    const int b = blk / NCHK;
    const int chunk = blk % NCHK;
    const int l0 = chunk * TBK;
    const int tid = threadIdx.x;
    const int h = tid >> 4;
    const int dq = (tid & 15) * 4;
    const int kvi = kvidx[b];
    const int slot = kvi % L;
    const int seq = min(kvi + 1, L);
    const int nvalid = min(TBK, max(0, seq - l0));

    const float* qp = g_qkv + b * HD + h * D + dq;
    const float q0 = bfr(qp[0]), q1 = bfr(qp[1]), q2 = bfr(qp[2]), q3 = bfr(qp[3]);

    __shared__ float slog[H][TBK + 1];

    const float4* src = reinterpret_cast<const float4*>(
        kk + ((size_t)b * L + l0) * HD) + tid;
    float4* dst = reinterpret_cast<float4*>(
        okey + ((size_t)b * L + l0) * HD) + tid;

    if (slot < l0 || slot >= l0 + TBK) {
        // hot path: pure streaming copy + dot
#pragma unroll 8
        for (int r = 0; r < TBK; r++) {
            float4 k4 = __ldcs(&src[(size_t)r * (HD / 4)]);
            __stcs(&dst[(size_t)r * (HD / 4)], k4);
            float s = bfr(k4.x) * q0 + bfr(k4.y) * q1 + bfr(k4.z) * q2 + bfr(k4.w) * q3;
            s += __shfl_down_sync(0xffffffffu, s, 8, 16);
            s += __shfl_down_sync(0xffffffffu, s, 4, 16);
            s += __shfl_down_sync(0xffffffffu, s, 2, 16);
            s += __shfl_down_sync(0xffffffffu, s, 1, 16);
            if ((tid & 15) == 0) slog[h][r] = s * 0.125f;   // 1/sqrt(64)
        }
    } else {
        const float4 knew = reinterpret_cast<const float4*>(
            g_qkv + (size_t)(B + b) * HD)[tid];
#pragma unroll 4
        for (int r = 0; r < TBK; r++) {
            float4 k4 = (l0 + r == slot) ? knew : __ldcs(&src[(size_t)r * (HD / 4)]);
            __stcs(&dst[(size_t)r * (HD / 4)], k4);
            float s = bfr(k4.x) * q0 + bfr(k4.y) * q1 + bfr(k4.z) * q2 + bfr(k4.w) * q3;
            s += __shfl_down_sync(0xffffffffu, s, 8, 16);
            s += __shfl_down_sync(0xffffffffu, s, 4, 16);
            s += __shfl_down_sync(0xffffffffu, s, 2, 16);
            s += __shfl_down_sync(0xffffffffu, s, 1, 16);
            if ((tid & 15) == 0) slog[h][r] = s * 0.125f;
        }
    }
    __syncthreads();
    // write this block's logits: head h gets contiguous [l0, l0+TBK)
    float4 o;
    o.x = slog[h][dq]; o.y = slog[h][dq + 1];
    o.z = slog[h][dq + 2]; o.w = slog[h][dq + 3];
    *reinterpret_cast<float4*>(g_logits + (size_t)(b * H + h) * L + l0 + dq) = o;

    // per-chunk stats over the nvalid rows (16 lanes per head cooperate)
    float mloc = -CUDART_INF_F;
#pragma unroll
    for (int i = 0; i < 4; i++) {
        int r = dq + i;
        if (r < nvalid) mloc = fmaxf(mloc, slog[h][r]);
    }
    mloc = fmaxf(mloc, __shfl_xor_sync(0xffffffffu, mloc, 8, 16));
    mloc = fmaxf(mloc, __shfl_xor_sync(0xffffffffu, mloc, 4, 16));
    mloc = fmaxf(mloc, __shfl_xor_sync(0xffffffffu, mloc, 2, 16));
    mloc = fmaxf(mloc, __shfl_xor_sync(0xffffffffu, mloc, 1, 16));
    float sloc = 0.f;
#pragma unroll
    for (int i = 0; i < 4; i++) {
        int r = dq + i;
        if (r < nvalid) sloc += expf(slog[h][r] - mloc);
    }
    sloc += __shfl_down_sync(0xffffffffu, sloc, 8, 16);
    sloc += __shfl_down_sync(0xffffffffu, sloc, 4, 16);
    sloc += __shfl_down_sync(0xffffffffu, sloc, 2, 16);
    sloc += __shfl_down_sync(0xffffffffu, sloc, 1, 16);
    if ((tid & 15) == 0) {
        g_cmax[(size_t)(b * H + h) * NCHK + chunk] = mloc;
        g_csum[(size_t)(b * H + h) * NCHK + chunk] = sloc;
    }
}

// -------- stats combine: m = max_c m_c; s = sum_c s_c * exp(m_c - m) -----
__global__ __launch_bounds__(128) void stats_combine_k() {
    const int bh = blockIdx.x;
    const int tid = threadIdx.x;              // 128 = NCHK threads
    float mv = g_cmax[(size_t)bh * NCHK + tid];
    float sv = g_csum[(size_t)bh * NCHK + tid];
    __shared__ float red[128];
    red[tid] = mv;
    __syncthreads();
    for (int st = 64; st; st >>= 1) {
        if (tid < st) red[tid] = fmaxf(red[tid], red[tid + st]);
        __syncthreads();
    }
    const float m = red[0];
    __syncthreads();
    // empty chunks have mv=-inf, sv=0 -> 0 * exp(-inf) = 0 * 0 = 0
    red[tid] = sv * expf(mv - m);
    __syncthreads();
    for (int st = 64; st; st >>= 1) {
        if (tid < st) red[tid] += red[tid + st];
        __syncthreads();
    }
    if (tid == 0) { g_m[bh] = m; g_s[bh] = red[0]; }
}

// -------- fused V: cache copy + slot scatter + AV accumulate, one pass ----
__global__ __launch_bounds__(256) void fused_v_kernel(
        const float* __restrict__ kv, const int* __restrict__ kvidx,
        float* __restrict__ oval) {
    const int blk = blockIdx.x;
    const int b = blk / NCV;
    const int c = blk % NCV;
    const int l0 = c * TBV;
    const int tid = threadIdx.x;
    const int h = tid >> 4;
    const int dq = (tid & 15) * 4;
    const int seq = min(kvidx[b] + 1, L);
    const int slot = kvidx[b] % L;
    const int nvalid = min(TBV, seq - l0);           // may be <= 0

    __shared__ float pb[H][TBV];                      // 8 KB
#pragma unroll
    for (int i = 0; i < (H * TBV) / 256; i++) {
        int lin = tid + 256 * i;        // < 2048
        int k = lin >> 7;               // head 0..15
        int r = lin & (TBV - 1);        // row  0..127
        float p = 0.f;
        if (r < nvalid) {
            const int bhk = b * H + k;
            float lg = g_logits[(size_t)bhk * L + l0 + r];
            p = bfr(expf(lg - g_m[bhk]) / g_s[bhk]);   // probs.astype(bf16)
        }
        pb[k][r] = p;
    }
    __syncthreads();

    const float4* src = reinterpret_cast<const float4*>(
        kv + ((size_t)b * L + l0) * HD) + tid;
    float4* dst = reinterpret_cast<float4*>(
        oval + ((size_t)b * L + l0) * HD) + tid;

    float4 acc = make_float4(0.f, 0.f, 0.f, 0.f);
    if (slot < l0 || slot >= l0 + TBV) {
        // hot path: pure streaming copy + AV fma
#pragma unroll 8
        for (int r = 0; r < TBV; r++) {
            float4 v4 = __ldcs(&src[(size_t)r * (HD / 4)]);
            __stcs(&dst[(size_t)r * (HD / 4)], v4);
            float p = pb[h][r];
            acc.x = fmaf(p, bfr(v4.x), acc.x);
            acc.y = fmaf(p, bfr(v4.y), acc.y);
            acc.z = fmaf(p, bfr(v4.z), acc.z);
            acc.w = fmaf(p, bfr(v4.w), acc.w);
        }
    } else {
        const float4 vnew = reinterpret_cast<const float4*>(
            g_qkv + (size_t)(2 * B + b) * HD)[tid];
#pragma unroll 4
        for (int r = 0; r < TBV; r++) {
            float4 v4 = (l0 + r == slot) ? vnew : __ldcs(&src[(size_t)r * (HD / 4)]);
            __stcs(&dst[(size_t)r * (HD / 4)], v4);
            float p = pb[h][r];
            acc.x = fmaf(p, bfr(v4.x), acc.x);
            acc.y = fmaf(p, bfr(v4.y), acc.y);
            acc.z = fmaf(p, bfr(v4.z), acc.z);
            acc.w = fmaf(p, bfr(v4.w), acc.w);
        }
    }
    *reinterpret_cast<float4*>(
        g_accpart + ((size_t)(b * H + h) * NCV + c) * D + dq) = acc;
}

// -------- output projection: combine AV partials inline, split-K GEMV -----
__global__ __launch_bounds__(256) void oproj_partial_k(const float* __restrict__ Wo) {
    const int c = blockIdx.x;
    const int hd0 = c * (HD / NOC);    // chunk = 16 columns, all within head h0
    const int h0 = hd0 >> 6;
    const int d0 = hd0 & 63;
    __shared__ float xs[HD / NOC][B];
    const int tid = threadIdx.x;
    // combine AV chunk partials for this block's 16 attn columns (bf16-round)
    {
        const int b = tid >> 4, f = tid & 15;   // lanes: f fastest -> coalesced
        const float* ap = g_accpart + ((size_t)(b * H + h0) * NCV) * D + d0 + f;
        float t = 0.f;
#pragma unroll 8
        for (int ch = 0; ch < NCV; ch++) t += ap[(size_t)ch * D];
        xs[f][b] = bfr(t);
    }
    __syncthreads();
    float4 acc[B];
#pragma unroll
    for (int b = 0; b < B; b++) acc[b] = make_float4(0.f, 0.f, 0.f, 0.f);
    const float4* wp = reinterpret_cast<const float4*>(Wo + (size_t)hd0 * F) + tid;
#pragma unroll
    for (int f = 0; f < HD / NOC; f++) {
        float4 w4 = wp[(size_t)f * (F / 4)];
#pragma unroll
        for (int b = 0; b < B; b++) {
            float xb = xs[f][b];
            acc[b].x = fmaf(xb, w4.x, acc[b].x);
            acc[b].y = fmaf(xb, w4.y, acc[b].y);
            acc[b].z = fmaf(xb, w4.z, acc[b].z);
            acc[b].w = fmaf(xb, w4.w, acc[b].w);
        }
    }
    float* dst = g_o_part + (size_t)c * B * F;
#pragma unroll
    for (int b = 0; b < B; b++)
        reinterpret_cast<float4*>(dst + b * F)[tid] = acc[b];
}

__global__ __launch_bounds__(256) void oproj_reduce_k(
        const float* __restrict__ bo, float* __restrict__ y) {
    int g = blockIdx.x * 256 + threadIdx.x;   // < B*F
    int b = g >> 10, col = g & 1023;
    float s = 0.f;
#pragma unroll 8
    for (int c = 0; c < NOC; c++)
        s += g_o_part[(size_t)c * B * F + b * F + col];
    y[g] = s + bo[col];
}

// -------- launch --------
extern "C" void kernel_launch(void* const* d_in, const int* in_sizes, int n_in,
                              void* d_out, int out_size) {
    (void)in_sizes; (void)n_in; (void)out_size;
    const float* x    = (const float*)d_in[0];
    const float* kk   = (const float*)d_in[1];
    const float* kv   = (const float*)d_in[2];
    const int*   kvix = (const int*)  d_in[3];
    const float* Wq   = (const float*)d_in[4];
    const float* bq   = (const float*)d_in[5];
    const float* Wk   = (const float*)d_in[6];
    const float* bk   = (const float*)d_in[7];
    const float* Wv   = (const float*)d_in[8];
    const float* bv   = (const float*)d_in[9];
    const float* Wo   = (const float*)d_in[10];
    const float* bo   = (const float*)d_in[11];

    // Output layout (all float32): y[B*F], kv_key[B*L*HD], kv_value[B*L*HD],
    // new_idx[B] stored as float.
    float* out  = (float*)d_out;
    float* y    = out;
    float* okey = out + (size_t)B * F;
    float* oval = okey + (size_t)B * L * HD;
    float* oidx = oval + (size_t)B * L * HD;

    qkv_partial_k<<<dim3(NFC, 3), 256>>>(x, Wq, Wk, Wv);
    qkv_reduce_k<<<(3 * B * HD) / 256, 256>>>(bq, bk, bv, kvix, oidx);
    fused_k_kernel<<<B * NCHK, 256>>>(kk, kvix, okey);
    stats_combine_k<<<B * H, 128>>>();
    fused_v_kernel<<<B * NCV, 256>>>(kv, kvix, oval);
    oproj_partial_k<<<NOC, 256>>>(Wo);
    oproj_reduce_k<<<(B * F) / 256, 256>>>(bo, y);
}

// round 14
// speedup vs baseline: 1.0509x; 1.0509x over previous
#include <cuda_runtime.h>
#include <cuda_bf16.h>
#include <math_constants.h>

#define B 16
#define F 1024
#define H 16
#define D 64
#define L 8192
#define HD 1024            // H*D
#define NFC 32             // f-chunks for qkv split-K partials
#define NOC 64             // hd-chunks for out-proj partials
#define TBK 64             // K rows per block in fused K kernel
#define NCHK (L / TBK)     // 128 K-chunks per batch
#define TBV 128            // V rows per block in fused V kernel
#define NCV (L / TBV)      // 64 V-chunks per batch
#define RB 8               // row batch for MLP

// -------- device scratch (allocation-free: __device__ globals) --------
__device__ float g_qkv_part[3 * NFC * B * HD];      // 6 MB
__device__ float g_qkv[3 * B * HD];                 // q,k,v fp32 (+bias)
__device__ float g_logits[B * H * L];               // 8 MB fp32 logits
__device__ float g_cmax[B * H * NCHK];              // per-chunk max
__device__ float g_csum[B * H * NCHK];              // per-chunk sum(exp(l-m_c))
__device__ float g_m[B * H];
__device__ float g_s[B * H];
__device__ float g_accpart[B * H * NCV * D];        // 4 MB split AV partials
__device__ float g_o_part[NOC * B * F];             // 4 MB

__device__ __forceinline__ float bfr(float v) {
    // round-to-nearest-even through bf16, back to fp32 (matches astype(bf16))
    return __bfloat162float(__float2bfloat16(v));
}

// -------- QKV projection: split-K partial GEMV --------
__global__ __launch_bounds__(256) void qkv_partial_k(
        const float* __restrict__ x,
        const float* __restrict__ Wq, const float* __restrict__ Wk,
        const float* __restrict__ Wv) {
    const int fc = blockIdx.x, w = blockIdx.y;
    const float* Wt = (w == 0) ? Wq : ((w == 1) ? Wk : Wv);
    const int f0 = fc * (F / NFC);
    __shared__ float xs[F / NFC][B];
    const int tid = threadIdx.x;
    for (int i = tid; i < (F / NFC) * B; i += 256) {
        int f = i >> 4, b = i & 15;
        xs[f][b] = x[b * F + f0 + f];
    }
    __syncthreads();
    float4 acc[B];
#pragma unroll
    for (int b = 0; b < B; b++) acc[b] = make_float4(0.f, 0.f, 0.f, 0.f);
    const float4* wp = reinterpret_cast<const float4*>(Wt + (size_t)f0 * HD) + tid;
#pragma unroll 4
    for (int f = 0; f < F / NFC; f++) {
        float4 w4 = wp[(size_t)f * (HD / 4)];
#pragma unroll
        for (int b = 0; b < B; b++) {
            float xb = xs[f][b];
            acc[b].x = fmaf(xb, w4.x, acc[b].x);
            acc[b].y = fmaf(xb, w4.y, acc[b].y);
            acc[b].z = fmaf(xb, w4.z, acc[b].z);
            acc[b].w = fmaf(xb, w4.w, acc[b].w);
        }
    }
    float* dst = g_qkv_part + (size_t)(w * NFC + fc) * B * HD;
#pragma unroll
    for (int b = 0; b < B; b++)
        reinterpret_cast<float4*>(dst + b * HD)[tid] = acc[b];
}

// Reduce partials + bias into g_qkv; write new_idx (as float — output dtype).
__global__ __launch_bounds__(256) void qkv_reduce_k(
        const float* __restrict__ bq, const float* __restrict__ bk,
        const float* __restrict__ bv, const int* __restrict__ kvidx,
        float* __restrict__ oidx) {
    int g = blockIdx.x * 256 + threadIdx.x;      // < 3*B*HD = 49152
    int w = g >> 14;
    int r = g & 16383;
    int b = r >> 10;
    int col = r & 1023;
    float s = 0.f;
#pragma unroll 8
    for (int c = 0; c < NFC; c++)
        s += g_qkv_part[(size_t)(w * NFC + c) * B * HD + b * HD + col];
    const float* bias = (w == 0) ? bq : ((w == 1) ? bk : bv);
    g_qkv[(w * B + b) * HD + col] = s + bias[col];
    if (w == 0 && col == 0) oidx[b] = (float)(kvidx[b] + 1);
}

// -------- fused K: cache copy + slot scatter + logits + chunk softmax stats
// grid = B * NCHK blocks, 256 threads. Thread tid owns head h=tid/16,
// d-range (tid%16)*4..+3 of every 4KB row. Batch-of-8 phases: 8 loads
// back-to-back (MLP 8), 8 stores, then 8 independent dot/shfl chains.
__global__ __launch_bounds__(256) void fused_k_kernel(
        const float* __restrict__ kk, const int* __restrict__ kvidx,
        float* __restrict__ okey) {
    const int blk = blockIdx.x;
    const int b = blk / NCHK;
    const int chunk = blk % NCHK;
    const int l0 = chunk * TBK;
    const int tid = threadIdx.x;
    const int h = tid >> 4;
    const int dq = (tid & 15) * 4;
    const int kvi = kvidx[b];
    const int slot = kvi % L;
    const int seq = min(kvi + 1, L);
    const int nvalid = min(TBK, max(0, seq - l0));

    const float* qp = g_qkv + b * HD + h * D + dq;
    const float q0 = bfr(qp[0]), q1 = bfr(qp[1]), q2 = bfr(qp[2]), q3 = bfr(qp[3]);

    __shared__ float slog[H][TBK + 1];

    const float4* src = reinterpret_cast<const float4*>(
        kk + ((size_t)b * L + l0) * HD) + tid;
    float4* dst = reinterpret_cast<float4*>(
        okey + ((size_t)b * L + l0) * HD) + tid;
    const float4 knew = reinterpret_cast<const float4*>(
        g_qkv + (size_t)(B + b) * HD)[tid];

    for (int rr = 0; rr < TBK; rr += RB) {
        float4 buf[RB];
#pragma unroll
        for (int i = 0; i < RB; i++)
            buf[i] = src[(size_t)(rr + i) * (HD / 4)];
#pragma unroll
        for (int i = 0; i < RB; i++)
            if (l0 + rr + i == slot) buf[i] = knew;
#pragma unroll
        for (int i = 0; i < RB; i++)
            dst[(size_t)(rr + i) * (HD / 4)] = buf[i];
#pragma unroll
        for (int i = 0; i < RB; i++) {
            float s = bfr(buf[i].x) * q0 + bfr(buf[i].y) * q1 +
                      bfr(buf[i].z) * q2 + bfr(buf[i].w) * q3;
            s += __shfl_down_sync(0xffffffffu, s, 8, 16);
            s += __shfl_down_sync(0xffffffffu, s, 4, 16);
            s += __shfl_down_sync(0xffffffffu, s, 2, 16);
            s += __shfl_down_sync(0xffffffffu, s, 1, 16);
            if ((tid & 15) == 0) slog[h][rr + i] = s * 0.125f;   // 1/sqrt(64)
        }
    }
    __syncthreads();
    // write this block's logits: head h gets contiguous [l0, l0+TBK)
    float4 o;
    o.x = slog[h][dq]; o.y = slog[h][dq + 1];
    o.z = slog[h][dq + 2]; o.w = slog[h][dq + 3];
    *reinterpret_cast<float4*>(g_logits + (size_t)(b * H + h) * L + l0 + dq) = o;

    // per-chunk stats over the nvalid rows (16 lanes per head cooperate)
    float mloc = -CUDART_INF_F;
#pragma unroll
    for (int i = 0; i < 4; i++) {
        int r = dq + i;
        if (r < nvalid) mloc = fmaxf(mloc, slog[h][r]);
    }
    mloc = fmaxf(mloc, __shfl_xor_sync(0xffffffffu, mloc, 8, 16));
    mloc = fmaxf(mloc, __shfl_xor_sync(0xffffffffu, mloc, 4, 16));
    mloc = fmaxf(mloc, __shfl_xor_sync(0xffffffffu, mloc, 2, 16));
    mloc = fmaxf(mloc, __shfl_xor_sync(0xffffffffu, mloc, 1, 16));
    float sloc = 0.f;
#pragma unroll
    for (int i = 0; i < 4; i++) {
        int r = dq + i;
        if (r < nvalid) sloc += expf(slog[h][r] - mloc);
    }
    sloc += __shfl_down_sync(0xffffffffu, sloc, 8, 16);
    sloc += __shfl_down_sync(0xffffffffu, sloc, 4, 16);
    sloc += __shfl_down_sync(0xffffffffu, sloc, 2, 16);
    sloc += __shfl_down_sync(0xffffffffu, sloc, 1, 16);
    if ((tid & 15) == 0) {
        g_cmax[(size_t)(b * H + h) * NCHK + chunk] = mloc;
        g_csum[(size_t)(b * H + h) * NCHK + chunk] = sloc;
    }
}

// -------- stats combine: m = max_c m_c; s = sum_c s_c * exp(m_c - m) -----
__global__ __launch_bounds__(128) void stats_combine_k() {
    const int bh = blockIdx.x;
    const int tid = threadIdx.x;              // 128 = NCHK threads
    float mv = g_cmax[(size_t)bh * NCHK + tid];
    float sv = g_csum[(size_t)bh * NCHK + tid];
    __shared__ float red[128];
    red[tid] = mv;
    __syncthreads();
    for (int st = 64; st; st >>= 1) {
        if (tid < st) red[tid] = fmaxf(red[tid], red[tid + st]);
        __syncthreads();
    }
    const float m = red[0];
    __syncthreads();
    // empty chunks have mv=-inf, sv=0 -> 0 * exp(-inf) = 0 * 0 = 0
    red[tid] = sv * expf(mv - m);
    __syncthreads();
    for (int st = 64; st; st >>= 1) {
        if (tid < st) red[tid] += red[tid + st];
        __syncthreads();
    }
    if (tid == 0) { g_m[bh] = m; g_s[bh] = red[0]; }
}

// -------- fused V: cache copy + slot scatter + AV accumulate, one pass ----
__global__ __launch_bounds__(256) void fused_v_kernel(
        const float* __restrict__ kv, const int* __restrict__ kvidx,
        float* __restrict__ oval) {
    const int blk = blockIdx.x;
    const int b = blk / NCV;
    const int c = blk % NCV;
    const int l0 = c * TBV;
    const int tid = threadIdx.x;
    const int h = tid >> 4;
    const int dq = (tid & 15) * 4;
    const int seq = min(kvidx[b] + 1, L);
    const int slot = kvidx[b] % L;
    const int nvalid = min(TBV, seq - l0);           // may be <= 0

    __shared__ float pb[H][TBV];                      // 8 KB
#pragma unroll
    for (int i = 0; i < (H * TBV) / 256; i++) {
        int lin = tid + 256 * i;        // < 2048
        int k = lin >> 7;               // head 0..15
        int r = lin & (TBV - 1);        // row  0..127
        float p = 0.f;
        if (r < nvalid) {
            const int bhk = b * H + k;
            float lg = g_logits[(size_t)bhk * L + l0 + r];
            p = bfr(expf(lg - g_m[bhk]) / g_s[bhk]);   // probs.astype(bf16)
        }
        pb[k][r] = p;
    }
    __syncthreads();

    const float4* src = reinterpret_cast<const float4*>(
        kv + ((size_t)b * L + l0) * HD) + tid;
    float4* dst = reinterpret_cast<float4*>(
        oval + ((size_t)b * L + l0) * HD) + tid;
    const float4 vnew = reinterpret_cast<const float4*>(
        g_qkv + (size_t)(2 * B + b) * HD)[tid];

    float4 acc = make_float4(0.f, 0.f, 0.f, 0.f);
    for (int rr = 0; rr < TBV; rr += RB) {
        float4 buf[RB];
#pragma unroll
        for (int i = 0; i < RB; i++)
            buf[i] = src[(size_t)(rr + i) * (HD / 4)];
#pragma unroll
        for (int i = 0; i < RB; i++)
            if (l0 + rr + i == slot) buf[i] = vnew;
#pragma unroll
        for (int i = 0; i < RB; i++)
            dst[(size_t)(rr + i) * (HD / 4)] = buf[i];
#pragma unroll
        for (int i = 0; i < RB; i++) {
            float p = pb[h][rr + i];
            acc.x = fmaf(p, bfr(buf[i].x), acc.x);
            acc.y = fmaf(p, bfr(buf[i].y), acc.y);
            acc.z = fmaf(p, bfr(buf[i].z), acc.z);
            acc.w = fmaf(p, bfr(buf[i].w), acc.w);
        }
    }
    *reinterpret_cast<float4*>(
        g_accpart + ((size_t)(b * H + h) * NCV + c) * D + dq) = acc;
}

// -------- output projection: combine AV partials inline, split-K GEMV -----
__global__ __launch_bounds__(256) void oproj_partial_k(const float* __restrict__ Wo) {
    const int c = blockIdx.x;
    const int hd0 = c * (HD / NOC);    // chunk = 16 columns, all within head h0
    const int h0 = hd0 >> 6;
    const int d0 = hd0 & 63;
    __shared__ float xs[HD / NOC][B];
    const int tid = threadIdx.x;
    // combine AV chunk partials for this block's 16 attn columns (bf16-round)
    {
        const int b = tid >> 4, f = tid & 15;   // lanes: f fastest -> coalesced
        const float* ap = g_accpart + ((size_t)(b * H + h0) * NCV) * D + d0 + f;
        float t = 0.f;
#pragma unroll 8
        for (int ch = 0; ch < NCV; ch++) t += ap[(size_t)ch * D];
        xs[f][b] = bfr(t);
    }
    __syncthreads();
    float4 acc[B];
#pragma unroll
    for (int b = 0; b < B; b++) acc[b] = make_float4(0.f, 0.f, 0.f, 0.f);
    const float4* wp = reinterpret_cast<const float4*>(Wo + (size_t)hd0 * F) + tid;
#pragma unroll
    for (int f = 0; f < HD / NOC; f++) {
        float4 w4 = wp[(size_t)f * (F / 4)];
#pragma unroll
        for (int b = 0; b < B; b++) {
            float xb = xs[f][b];
            acc[b].x = fmaf(xb, w4.x, acc[b].x);
            acc[b].y = fmaf(xb, w4.y, acc[b].y);
            acc[b].z = fmaf(xb, w4.z, acc[b].z);
            acc[b].w = fmaf(xb, w4.w, acc[b].w);
        }
    }
    float* dst = g_o_part + (size_t)c * B * F;
#pragma unroll
    for (int b = 0; b < B; b++)
        reinterpret_cast<float4*>(dst + b * F)[tid] = acc[b];
}

__global__ __launch_bounds__(256) void oproj_reduce_k(
        const float* __restrict__ bo, float* __restrict__ y) {
    int g = blockIdx.x * 256 + threadIdx.x;   // < B*F
    int b = g >> 10, col = g & 1023;
    float s = 0.f;
#pragma unroll 8
    for (int c = 0; c < NOC; c++)
        s += g_o_part[(size_t)c * B * F + b * F + col];
    y[g] = s + bo[col];
}

// -------- launch --------
extern "C" void kernel_launch(void* const* d_in, const int* in_sizes, int n_in,
                              void* d_out, int out_size) {
    (void)in_sizes; (void)n_in; (void)out_size;
    const float* x    = (const float*)d_in[0];
    const float* kk   = (const float*)d_in[1];
    const float* kv   = (const float*)d_in[2];
    const int*   kvix = (const int*)  d_in[3];
    const float* Wq   = (const float*)d_in[4];
    const float* bq   = (const float*)d_in[5];
    const float* Wk   = (const float*)d_in[6];
    const float* bk   = (const float*)d_in[7];
    const float* Wv   = (const float*)d_in[8];
    const float* bv   = (const float*)d_in[9];
    const float* Wo   = (const float*)d_in[10];
    const float* bo   = (const float*)d_in[11];

    // Output layout (all float32): y[B*F], kv_key[B*L*HD], kv_value[B*L*HD],
    // new_idx[B] stored as float.
    float* out  = (float*)d_out;
    float* y    = out;
    float* okey = out + (size_t)B * F;
    float* oval = okey + (size_t)B * L * HD;
    float* oidx = oval + (size_t)B * L * HD;

    qkv_partial_k<<<dim3(NFC, 3), 256>>>(x, Wq, Wk, Wv);
    qkv_reduce_k<<<(3 * B * HD) / 256, 256>>>(bq, bk, bv, kvix, oidx);
    fused_k_kernel<<<B * NCHK, 256>>>(kk, kvix, okey);
    stats_combine_k<<<B * H, 128>>>();
    fused_v_kernel<<<B * NCV, 256>>>(kv, kvix, oval);
    oproj_partial_k<<<NOC, 256>>>(Wo);
    oproj_reduce_k<<<(B * F) / 256, 256>>>(bo, y);
}